// round 7
// baseline (speedup 1.0000x reference)
#include <cuda_runtime.h>

#define BATCH 4
#define CCH   32
#define HH    512
#define WW    960
#define HT    128
#define WT    240
#define HW    (HH*WW)      // 491520
#define HTWT  (HT*WT)      // 30720

__global__ __launch_bounds__(256)
void tile_warp_kernel(const float* __restrict__ tp,
                      const float* __restrict__ fl,
                      const float* __restrict__ fr,
                      float* __restrict__ out)
{
    // One thread per (b, ht, x): owns all 4 rows (i=0..3) of its tile column.
    int tid = blockIdx.x * blockDim.x + threadIdx.x;   // B*HT*WW = 491520
    int x  = tid % WW;
    int t  = tid / WW;
    int ht = t % HT;
    int b  = t / HT;
    int wt = x >> 2, j = x & 3;

    int tb = (b * 3 * HT + ht) * WT + wt;
    float d  = tp[tb];
    float dx = tp[tb + HTWT];
    float dy = tp[tb + 2 * HTWT];

    // s_i = x - disp_i,  disp_i = d + (i-1.5)*dy + (j-1.5)*dx
    float s0 = (float)x - d - ((float)j - 1.5f) * dx + 1.5f * dy;

    float w[4]; int x0[4];
    bool fast = true;
#pragma unroll
    for (int i = 0; i < 4; i++) {
        float s = s0 - (float)i * dy;
        float f = floorf(s);
        w[i]  = s - f;
        x0[i] = (int)f;
        fast = fast && (x0[i] >= 1) && (x0[i] <= WW - 3);
    }

    const float* flp = fl + (size_t)b * CCH * HW + (size_t)(ht * 4) * WW + x;
    const float* frp = fr + (size_t)b * CCH * HW + (size_t)(ht * 4) * WW;

    float acc[12];
#pragma unroll
    for (int k = 0; k < 12; k++) acc[k] = 0.f;

    if (fast) {
        // Interior: no clamps, all masks == 1.
#pragma unroll 2
        for (int c = 0; c < CCH; c++) {
            int co = c * HW;
#pragma unroll
            for (int i = 0; i < 4; i++) {
                float a = __ldcs(flp + co + i * WW);
                const float* r = frp + co + i * WW + x0[i];
                float g0 = __ldg(r - 1);
                float g1 = __ldg(r);
                float g2 = __ldg(r + 1);
                float g3 = __ldg(r + 2);
                float wi = w[i];
                acc[i*3+0] += fabsf(a - (g2 + wi * (g3 - g2)));  // dd=-1
                acc[i*3+1] += fabsf(a - (g1 + wi * (g2 - g1)));  // dd= 0
                acc[i*3+2] += fabsf(a - (g0 + wi * (g1 - g0)));  // dd=+1
            }
        }
    } else {
        // Border: clamped taps + validity masks (matches reference exactly).
        float m[12]; int ii[16];
#pragma unroll
        for (int i = 0; i < 4; i++) {
            float s = s0 - (float)i * dy;
            m[i*3+0] = (s >= -1.f && s <= (float)(WW - 2)) ? 1.f : 0.f;
            m[i*3+1] = (s >=  0.f && s <= (float)(WW - 1)) ? 1.f : 0.f;
            m[i*3+2] = (s >=  1.f && s <= (float)(WW))     ? 1.f : 0.f;
            ii[i*4+0] = min(max(x0[i] - 1, 0), WW - 1);
            ii[i*4+1] = min(max(x0[i]    , 0), WW - 1);
            ii[i*4+2] = min(max(x0[i] + 1, 0), WW - 1);
            ii[i*4+3] = min(max(x0[i] + 2, 0), WW - 1);
        }
        for (int c = 0; c < CCH; c++) {
            int co = c * HW;
#pragma unroll
            for (int i = 0; i < 4; i++) {
                float a = __ldcs(flp + co + i * WW);
                const float* r = frp + co + i * WW;
                float g0 = __ldg(r + ii[i*4+0]);
                float g1 = __ldg(r + ii[i*4+1]);
                float g2 = __ldg(r + ii[i*4+2]);
                float g3 = __ldg(r + ii[i*4+3]);
                float wi = w[i];
                acc[i*3+0] += fabsf(a - m[i*3+0] * (g2 + wi * (g3 - g2)));
                acc[i*3+1] += fabsf(a - m[i*3+1] * (g1 + wi * (g2 - g1)));
                acc[i*3+2] += fabsf(a - m[i*3+2] * (g0 + wi * (g1 - g0)));
            }
        }
    }

    int ob = (b * 48 * HT + ht) * WT + wt;
#pragma unroll
    for (int i = 0; i < 4; i++) {
#pragma unroll
        for (int h = 0; h < 3; h++) {
            out[ob + (h * 16 + i * 4 + j) * HTWT] = acc[i*3 + h];
        }
    }
}

extern "C" void kernel_launch(void* const* d_in, const int* in_sizes, int n_in,
                              void* d_out, int out_size)
{
    const float* tp = nullptr;
    const float* big[2] = {nullptr, nullptr};
    int nbig = 0;
    for (int k = 0; k < n_in; k++) {
        if (in_sizes[k] == BATCH * 3 * HTWT) {
            tp = (const float*)d_in[k];
        } else if (nbig < 2) {
            big[nbig++] = (const float*)d_in[k];
        }
    }
    const float* fl = big[0];
    const float* fr = big[1];
    float* out = (float*)d_out;

    int total = BATCH * HT * WW;          // 491,520 threads
    int threads = 256;
    int blocks = (total + threads - 1) / threads;  // 1920
    tile_warp_kernel<<<blocks, threads>>>(tp, fl, fr, out);
}